// round 10
// baseline (speedup 1.0000x reference)
#include <cuda_runtime.h>
#include <cuda_fp16.h>
#include <cstdint>

// ---------------- problem constants ----------------
#define BATCH 4
#define NNODE 4096
#define NEDGE 65536
#define DIN   128
#define DBOND 64
#define DOUT  128
#define NT    4
#define DCAT  320

#define TM    128
#define TB    256                  // 8 warps; 2 CTAs/SM
#define NCH_A 5
#define NCH_B 2
#define WSTR2 36
#define WTILE (128*WSTR2)          // 4608 u32
#define ASTR2 36
#define ACH   (TM*ASTR2)           // 4608 u32
#define HSTR2 68
#define NTILES (NEDGE/TM + NT)     // 516
#define NHB   256

#define PB_ZERO 2048
#define PB_HIST NHB
#define PB_PREPW (2*NT*(NCH_A+NCH_B))

// ---------------- device scratch ----------------
__device__ int g_poff[NT + 1];
__device__ __align__(16) int g_bcnt[NHB * NT];
__device__ __align__(16) int g_bbase[NHB * NT];
__device__ __align__(16) int g_order[NEDGE + NT * TM];
__device__ uint32_t g_WAh[2 * NT * NCH_A * WTILE];
__device__ uint32_t g_WBh[2 * NT * NCH_B * WTILE];

// ---------------- helpers ----------------
__device__ __forceinline__ float lrelu(float x) { return x > 0.f ? x : 0.01f * x; }
__device__ __forceinline__ uint32_t h2bits(float a, float b) {
    __half2 h = __floats2half2_rn(a, b);
    return *reinterpret_cast<uint32_t*>(&h);
}
__device__ __forceinline__ uint32_t smem_u32(const void* p) {
    uint32_t a;
    asm("{ .reg .u64 t; cvta.to.shared.u64 t, %1; cvt.u32.u64 %0, t; }" : "=r"(a) : "l"(p));
    return a;
}
__device__ __forceinline__ void cpasync16(uint32_t saddr, const void* g) {
    asm volatile("cp.async.ca.shared.global [%0], [%1], 16;" :: "r"(saddr), "l"(g));
}
#define CP_COMMIT() asm volatile("cp.async.commit_group;" ::: "memory")
#define CP_WAIT0()  asm volatile("cp.async.wait_group 0;" ::: "memory")
__device__ __forceinline__ void red2(float* addr, float a, float b) {
    asm volatile("red.global.add.v2.f32 [%0], {%1, %2};" :: "l"(addr), "f"(a), "f"(b) : "memory");
}
__device__ __forceinline__ void ldsm4(uint32_t& r0, uint32_t& r1, uint32_t& r2, uint32_t& r3,
                                      uint32_t addr) {
    asm volatile("ldmatrix.sync.aligned.m8n8.x4.shared.b16 {%0,%1,%2,%3}, [%4];"
        : "=r"(r0), "=r"(r1), "=r"(r2), "=r"(r3) : "r"(addr));
}
__device__ __forceinline__ void mma16(float* d, uint32_t a0, uint32_t a1, uint32_t a2, uint32_t a3,
                                      uint32_t b0, uint32_t b1) {
    asm volatile(
        "mma.sync.aligned.m16n8k16.row.col.f32.f16.f16.f32 "
        "{%0,%1,%2,%3},{%4,%5,%6,%7},{%8,%9},{%0,%1,%2,%3};"
        : "+f"(d[0]), "+f"(d[1]), "+f"(d[2]), "+f"(d[3])
        : "r"(a0), "r"(a1), "r"(a2), "r"(a3), "r"(b0), "r"(b1));
}

// ---------------- prep kernels (unchanged) ----------------
__global__ void k_prep(float* __restrict__ out, int n_out, const int* __restrict__ uc,
                       const float* __restrict__ W1a, const float* __restrict__ W2a,
                       const float* __restrict__ W1b, const float* __restrict__ W2b) {
    __shared__ int cnt[NT];
    __shared__ float smw[64 * 129];
    const int blk = blockIdx.x;
    const int tid = threadIdx.x;

    if (blk < PB_ZERO) {
        int i = blk * 256 + tid;
        if (i < (n_out >> 2)) ((float4*)out)[i] = make_float4(0.f, 0.f, 0.f, 0.f);
        if (i < (NEDGE + NT * TM) / 4) ((int4*)g_order)[i] = make_int4(-1, -1, -1, -1);
        return;
    }
    if (blk < PB_ZERO + PB_HIST) {
        int hb = blk - PB_ZERO;
        if (tid < NT) cnt[tid] = 0;
        __syncthreads();
        atomicAdd(&cnt[uc[hb * 256 + tid]], 1);
        __syncthreads();
        if (tid < NT) g_bcnt[hb * NT + tid] = cnt[tid];
        return;
    }
    int wb = blk - PB_ZERO - PB_HIST;
    bool isA = wb < 2 * NT * NCH_A;
    int c, pt;
    if (isA) { c = wb % NCH_A; pt = wb / NCH_A; }
    else     { int j = wb - 2 * NT * NCH_A; c = j % NCH_B; pt = j / NCH_B; }
    int t = pt & 3, p = pt >> 2;
    int ld = isA ? DCAT : DOUT;
    const float* W = isA ? (p ? W2a : W1a) : (p ? W2b : W1b);
#pragma unroll
    for (int i = 0; i < 32; i++) {
        int lin = tid + 256 * i;
        int k = lin >> 7, n = lin & 127;
        smw[k * 129 + n] = W[((size_t)t * ld + c * 64 + k) * DOUT + n];
    }
    __syncthreads();
    uint32_t* dst = isA ? (g_WAh + (size_t)(pt * NCH_A + c) * WTILE)
                        : (g_WBh + (size_t)(pt * NCH_B + c) * WTILE);
#pragma unroll
    for (int i = 0; i < 16; i++) {
        int lin = tid + 256 * i;
        int n = lin >> 5, k2 = lin & 31;
        dst[n * WSTR2 + k2] = h2bits(smw[(2 * k2) * 129 + n], smw[(2 * k2 + 1) * 129 + n]);
    }
}

__global__ void k_scan() {
    __shared__ int wsum[8][NT];
    __shared__ int tot[NT];
    int tid = threadIdx.x, lane = tid & 31, w = tid >> 5;
    int4 v = ((const int4*)g_bcnt)[tid];
    int4 orig = v;
#pragma unroll
    for (int d = 1; d < 32; d <<= 1) {
        int x = __shfl_up_sync(~0u, v.x, d), y = __shfl_up_sync(~0u, v.y, d);
        int z = __shfl_up_sync(~0u, v.z, d), q = __shfl_up_sync(~0u, v.w, d);
        if (lane >= d) { v.x += x; v.y += y; v.z += z; v.w += q; }
    }
    if (lane == 31) { wsum[w][0] = v.x; wsum[w][1] = v.y; wsum[w][2] = v.z; wsum[w][3] = v.w; }
    __syncthreads();
    if (tid == 0) {
        int a0 = 0, a1 = 0, a2 = 0, a3 = 0;
        for (int i = 0; i < 8; i++) {
            int t0 = wsum[i][0], t1 = wsum[i][1], t2 = wsum[i][2], t3 = wsum[i][3];
            wsum[i][0] = a0; wsum[i][1] = a1; wsum[i][2] = a2; wsum[i][3] = a3;
            a0 += t0; a1 += t1; a2 += t2; a3 += t3;
        }
        tot[0] = a0; tot[1] = a1; tot[2] = a2; tot[3] = a3;
    }
    __syncthreads();
    int e0 = v.x + wsum[w][0] - orig.x;
    int e1 = v.y + wsum[w][1] - orig.y;
    int e2 = v.z + wsum[w][2] - orig.z;
    int e3 = v.w + wsum[w][3] - orig.w;
    int p0 = 0;
    int p1 = p0 + ((tot[0] + TM - 1) / TM) * TM;
    int p2 = p1 + ((tot[1] + TM - 1) / TM) * TM;
    int p3 = p2 + ((tot[2] + TM - 1) / TM) * TM;
    int p4 = p3 + ((tot[3] + TM - 1) / TM) * TM;
    int4 bb; bb.x = p0 + e0; bb.y = p1 + e1; bb.z = p2 + e2; bb.w = p3 + e3;
    ((int4*)g_bbase)[tid] = bb;
    if (tid == 0) {
        g_poff[0] = p0; g_poff[1] = p1; g_poff[2] = p2; g_poff[3] = p3; g_poff[4] = p4;
    }
}

__global__ void k_scatter(const int* __restrict__ uc) {
    __shared__ int base[NT];
    __shared__ int cur[NT];
    int tid = threadIdx.x;
    if (tid < NT) { base[tid] = g_bbase[blockIdx.x * NT + tid]; cur[tid] = 0; }
    __syncthreads();
    int e = blockIdx.x * 256 + tid;
    int t = uc[e];
    int pos = atomicAdd(&cur[t], 1);
    g_order[base[t] + pos] = e;
}

// ---------------- fused kernel smem layout (u32 units) ----------------
#define OFA    0                       // 2 x 4608 (A chunk double buffer)
#define OFW    9216                    // 2 x 4608 (W double buffer)
#define OFH    18432                   // 128 x 68
#define OFRED  27136                   // 128
#define OFBIAS 27264                   // 6 x 128 = 768
#define OFE    28032
#define OFI1   28160
#define OFI2   28288
#define SMEM_U32 28416
#define SMEM_BYTES (SMEM_U32 * 4)      // 113664 -> 2 CTAs/SM

__device__ __forceinline__ void issueW(uint32_t sdst, const uint32_t* __restrict__ g, int tid) {
    const uint4* gs = (const uint4*)g;
#pragma unroll
    for (int i = 0; i < 5; i++) {
        int lin = tid + TB * i;
        if (lin < 1152) cpasync16(sdst + lin * 16, gs + lin);
    }
    CP_COMMIT();
}

__device__ __forceinline__ void gatherChunk(float4* pA, const float* __restrict__ sites,
                                            const float* __restrict__ bonds, int b,
                                            const int* sE, const int* sI1, const int* sI2,
                                            int c, int tid) {
#pragma unroll
    for (int i = 0; i < 8; i++) {
        int lin = tid + TB * i;
        int row = lin >> 4, col = (lin & 15) << 2;
        const float* src;
        if (c < 2)      src = sites + ((size_t)b * NNODE + sI1[row]) * DIN + c * 64 + col;
        else if (c < 4) src = sites + ((size_t)b * NNODE + sI2[row]) * DIN + (c - 2) * 64 + col;
        else { int e = sE[row]; if (e < 0) e = 0;
               src = bonds + ((size_t)b * NEDGE + e) * DBOND + col; }
        pA[i] = *(const float4*)src;
    }
}

__device__ __forceinline__ void stageChunk(uint32_t* __restrict__ Ab, const float4* pA, int tid) {
#pragma unroll
    for (int i = 0; i < 8; i++) {
        int lin = tid + TB * i;
        int row = lin >> 4, j = (lin & 15) << 1;
        uint2 v;
        v.x = h2bits(pA[i].x, pA[i].y);
        v.y = h2bits(pA[i].z, pA[i].w);
        *(uint2*)(Ab + row * ASTR2 + j) = v;
    }
}

// 32x64 warp tile over one k=64 chunk (used by both layers)
__device__ __forceinline__ void mma64(uint32_t aAddr, int astrB, uint32_t wAddr,
                                      float acc[2][8][4]) {
#pragma unroll
    for (int kk = 0; kk < 4; kk++) {
        const uint32_t kb = kk * 32;
        uint32_t bw[16];
        ldsm4(bw[0],  bw[1],  bw[2],  bw[3],  wAddr + kb);
        ldsm4(bw[4],  bw[5],  bw[6],  bw[7],  wAddr + 16 * WSTR2 * 4 + kb);
        ldsm4(bw[8],  bw[9],  bw[10], bw[11], wAddr + 32 * WSTR2 * 4 + kb);
        ldsm4(bw[12], bw[13], bw[14], bw[15], wAddr + 48 * WSTR2 * 4 + kb);
#pragma unroll
        for (int mt = 0; mt < 2; mt++) {
            uint32_t a0, a1, a2, a3;
            ldsm4(a0, a1, a2, a3, aAddr + mt * 16 * astrB + kb);
#pragma unroll
            for (int nt = 0; nt < 8; nt++)
                mma16(acc[mt][nt], a0, a1, a2, a3, bw[2 * nt], bw[2 * nt + 1]);
        }
    }
}

__global__ void __launch_bounds__(TB, 2) k_fused(
    const float* __restrict__ sites, const float* __restrict__ bonds,
    const int* __restrict__ idx1, const int* __restrict__ idx2,
    const float* __restrict__ b1a, const float* __restrict__ b1b,
    const float* __restrict__ b2a, const float* __restrict__ b2b,
    const float* __restrict__ Wa1, const float* __restrict__ ba1,
    const float* __restrict__ Wa2, const float* __restrict__ ba2,
    float* __restrict__ out)
{
    extern __shared__ uint32_t sm[];
    uint32_t* sH = sm + OFH;
    float* sRed  = (float*)(sm + OFRED);
    float* sBias = (float*)(sm + OFBIAS);
    int* sE  = (int*)(sm + OFE);
    int* sI1 = (int*)(sm + OFI1);
    int* sI2 = (int*)(sm + OFI2);

    const int tile  = blockIdx.x;
    const int start = tile * TM;
    if (start >= g_poff[NT]) return;
    int t = 0;
#pragma unroll
    for (int i = 1; i < NT; i++) if (start >= g_poff[i]) t = i;

    const int tid  = threadIdx.x;
    const int lane = tid & 31;
    const int wid  = tid >> 5;
    const int wm   = wid & 3;       // 4 row groups x 32
    const int wn   = wid >> 2;      // 2 col groups x 64
    const int grp  = lane >> 2;
    const int qq   = lane & 3;
    const int bb   = blockIdx.y;

    if (tid < TM) {
        int e = g_order[start + tid];
        sE[tid] = e;
        int es = e < 0 ? 0 : e;
        sI1[tid] = idx1[es];
        sI2[tid] = idx2[es];
    }
    if (tid < 128) {
        sBias[0 * 128 + tid] = b1a[t * DOUT + tid];
        sBias[1 * 128 + tid] = b1b[t * DOUT + tid];
        sBias[2 * 128 + tid] = Wa1[tid];
        sBias[3 * 128 + tid] = b2a[t * DOUT + tid];
        sBias[4 * 128 + tid] = b2b[t * DOUT + tid];
        sBias[5 * 128 + tid] = Wa2[tid];
    }
    __syncthreads();

    // ldmatrix lane offsets
    const int rA = wm * 32 + (lane & 7) + ((lane >> 3) & 1) * 8;
    const int nB = (lane & 7) + ((lane >> 4) & 1) * 8;
    const uint32_t sb = smem_u32(sm);
    const uint32_t aBase = sb + (uint32_t)(rA * ASTR2 + (lane >> 4) * 4) * 4;
    const uint32_t hBase = sb + (uint32_t)(OFH + rA * HSTR2 + (lane >> 4) * 4) * 4;
    const uint32_t wBase = sb + (uint32_t)(OFW + (wn * 64 + nB) * WSTR2 + ((lane >> 3) & 1) * 4) * 4;

    float4 pA[8];

    // prologue: W_A(p0, c0) -> Wbuf0; gather A chunk0
    issueW(sb + OFW * 4, g_WAh + (size_t)((0 * NT + t) * NCH_A) * WTILE, tid);
    gatherChunk(pA, sites, bonds, bb, sE, sI1, sI2, 0, tid);

#pragma unroll 1
    for (int p = 0; p < 2; ++p) {
        const uint32_t* gWA = g_WAh + (size_t)((p * NT + t) * NCH_A) * WTILE;
        const uint32_t* gWB = g_WBh + (size_t)((p * NT + t) * NCH_B) * WTILE;
        const float* sBla = sBias + (p * 3 + 0) * 128;
        const float* sBlb = sBias + (p * 3 + 1) * 128;
        const float* sWg  = sBias + (p * 3 + 2) * 128;
        const float bg = p ? ba2[0] : ba1[0];

        float acc[2][8][4];
#pragma unroll
        for (int mt = 0; mt < 2; mt++)
#pragma unroll
            for (int nt = 0; nt < 8; nt++)
#pragma unroll
                for (int i = 0; i < 4; i++) acc[mt][nt][i] = 0.f;

        // ---------------- layer A: [128x320] @ [320x128] ----------------
#pragma unroll
        for (int c = 0; c < NCH_A; c++) {
            const int s = c & 1;
            stageChunk(sm + OFA + s * ACH, pA, tid);
            CP_WAIT0();
            __syncthreads();
            if (c + 1 < NCH_A) {
                issueW(sb + (OFW + ((c + 1) & 1) * WTILE) * 4, gWA + (size_t)(c + 1) * WTILE, tid);
                gatherChunk(pA, sites, bonds, bb, sE, sI1, sI2, c + 1, tid);
            } else {
                issueW(sb + (OFW + WTILE) * 4, gWB, tid);   // W_B chunk0 -> buf1
            }
            mma64(aBase + (uint32_t)(s * ACH) * 4, ASTR2 * 4,
                  wBase + (uint32_t)(s * WTILE) * 4, acc);
        }

        // ---- epilogue A: H = fp16(lrelu(acc + bla)) ----
#pragma unroll
        for (int mt = 0; mt < 2; mt++) {
            int r = wm * 32 + mt * 16 + grp;
#pragma unroll
            for (int nt = 0; nt < 8; nt++) {
                int cc = wn * 64 + nt * 8 + 2 * qq;
                int col2 = wn * 32 + nt * 4 + qq;
                sH[r * HSTR2 + col2] =
                    h2bits(lrelu(acc[mt][nt][0] + sBla[cc]), lrelu(acc[mt][nt][1] + sBla[cc + 1]));
                sH[(r + 8) * HSTR2 + col2] =
                    h2bits(lrelu(acc[mt][nt][2] + sBla[cc]), lrelu(acc[mt][nt][3] + sBla[cc + 1]));
#pragma unroll
                for (int i = 0; i < 4; i++) acc[mt][nt][i] = 0.f;
            }
        }
        if (p == 0)   // gather phase-1 chunk0 under layer B
            gatherChunk(pA, sites, bonds, bb, sE, sI1, sI2, 0, tid);
        CP_WAIT0();
        __syncthreads();                       // H visible; W_B0 resident (buf1)

        // ---------------- layer B: out = H @ Wb ----------------
        issueW(sb + OFW * 4, gWB + WTILE, tid);   // W_B chunk1 -> buf0 (free after sync)
        mma64(hBase, HSTR2 * 4, wBase + (uint32_t)WTILE * 4, acc);
        CP_WAIT0();
        __syncthreads();                       // W_B1 resident
        mma64(hBase + 128, HSTR2 * 4, wBase, acc);
        __syncthreads();                       // W bufs + H free
        if (p == 0)                            // next phase W_A c0 -> buf0
            issueW(sb + OFW * 4, g_WAh + (size_t)((1 * NT + t) * NCH_A) * WTILE, tid);
        if (tid < TM) sRed[tid] = 0.f;
        __syncthreads();

        // ---- gate dot ----
#pragma unroll
        for (int mt = 0; mt < 2; mt++) {
            int r = wm * 32 + mt * 16 + grp;
            float d0 = 0.f, d1 = 0.f;
#pragma unroll
            for (int nt = 0; nt < 8; nt++) {
                int cc = wn * 64 + nt * 8 + 2 * qq;
                float w0 = sWg[cc], w1 = sWg[cc + 1];
                d0 += lrelu(acc[mt][nt][0] + sBlb[cc]) * w0
                    + lrelu(acc[mt][nt][1] + sBlb[cc + 1]) * w1;
                d1 += lrelu(acc[mt][nt][2] + sBlb[cc]) * w0
                    + lrelu(acc[mt][nt][3] + sBlb[cc + 1]) * w1;
            }
            d0 += __shfl_xor_sync(0xffffffffu, d0, 1);
            d0 += __shfl_xor_sync(0xffffffffu, d0, 2);
            d1 += __shfl_xor_sync(0xffffffffu, d1, 1);
            d1 += __shfl_xor_sync(0xffffffffu, d1, 2);
            if (qq == 0) {
                atomicAdd(&sRed[r], d0);
                atomicAdd(&sRed[r + 8], d1);
            }
        }
        __syncthreads();

        // ---- gate apply + per-phase vector-red scatter ----
#pragma unroll
        for (int mt = 0; mt < 2; mt++) {
            int r = wm * 32 + mt * 16 + grp;
            float sig0 = 1.f / (1.f + __expf(-(sRed[r] + bg)));
            float sig1 = 1.f / (1.f + __expf(-(sRed[r + 8] + bg)));
            bool v0 = sE[r] >= 0, v1 = sE[r + 8] >= 0;
            float* d0p = out + ((size_t)bb * NNODE + sI2[r]) * DOUT;
            float* d1p = out + ((size_t)bb * NNODE + sI2[r + 8]) * DOUT;
#pragma unroll
            for (int nt = 0; nt < 8; nt++) {
                int cc = wn * 64 + nt * 8 + 2 * qq;
                if (v0) {
                    red2(d0p + cc,
                         sig0 * lrelu(acc[mt][nt][0] + sBlb[cc]),
                         sig0 * lrelu(acc[mt][nt][1] + sBlb[cc + 1]));
                }
                if (v1) {
                    red2(d1p + cc,
                         sig1 * lrelu(acc[mt][nt][2] + sBlb[cc]),
                         sig1 * lrelu(acc[mt][nt][3] + sBlb[cc + 1]));
                }
            }
        }
        // no sync needed: next phase's first write (stage -> Abuf0) has no
        // readers since the prior layer-A loop completed before this point.
    } // p
}

// ---------------- launcher ----------------
extern "C" void kernel_launch(void* const* d_in, const int* in_sizes, int n_in,
                              void* d_out, int out_size) {
    (void)in_sizes; (void)n_in;
    const float* sites = (const float*)d_in[0];
    const float* bonds = (const float*)d_in[1];
    const int*   idx1  = (const int*)d_in[2];
    const int*   idx2  = (const int*)d_in[3];
    const int*   uc    = (const int*)d_in[4];
    const float* W1a = (const float*)d_in[5];
    const float* b1a = (const float*)d_in[6];
    const float* W1b = (const float*)d_in[7];
    const float* b1b = (const float*)d_in[8];
    const float* W2a = (const float*)d_in[9];
    const float* b2a = (const float*)d_in[10];
    const float* W2b = (const float*)d_in[11];
    const float* b2b = (const float*)d_in[12];
    const float* Wa1 = (const float*)d_in[13];
    const float* ba1 = (const float*)d_in[14];
    const float* Wa2 = (const float*)d_in[15];
    const float* ba2 = (const float*)d_in[16];
    float* out = (float*)d_out;

    cudaFuncSetAttribute(k_fused, cudaFuncAttributeMaxDynamicSharedMemorySize, SMEM_BYTES);

    k_prep<<<PB_ZERO + PB_HIST + PB_PREPW, 256>>>(out, out_size, uc, W1a, W2a, W1b, W2b);
    k_scan<<<1, 256>>>();
    k_scatter<<<NHB, 256>>>(uc);
    dim3 grid(NTILES, BATCH);
    k_fused<<<grid, TB, SMEM_BYTES>>>(sites, bonds, idx1, idx2,
                                      b1a, b1b, b2a, b2b,
                                      Wa1, ba1, Wa2, ba2, out);
}

// round 11
// speedup vs baseline: 1.4196x; 1.4196x over previous
#include <cuda_runtime.h>
#include <cuda_fp16.h>
#include <cstdint>

// ---------------- problem constants ----------------
#define BATCH 4
#define NNODE 4096
#define NEDGE 65536
#define DIN   128
#define DBOND 64
#define DOUT  128
#define NT    4
#define DCAT  320

#define TM    128
#define TB    512                  // 16 warps
#define NCH_A 5
#define NCH_B 2
#define WSTR2 36
#define WTILE (128*WSTR2)          // 4608 u32
#define ASTR2 36
#define ACH   (TM*ASTR2)           // 4608 u32
#define HSTR2 68
#define NTILES (NEDGE/TM + NT)     // 516
#define NHB   256

#define PB_ZERO 2048
#define PB_HIST NHB
#define PB_PREPW (2*NT*(NCH_A+NCH_B))
#define PB_CVTS 256                 // sites fp32 -> fp16 conversion blocks

// ---------------- device scratch ----------------
__device__ int g_poff[NT + 1];
__device__ __align__(16) int g_bcnt[NHB * NT];
__device__ __align__(16) int g_bbase[NHB * NT];
__device__ __align__(16) int g_order[NEDGE + NT * TM];
__device__ uint32_t g_WAh[2 * NT * NCH_A * WTILE];
__device__ uint32_t g_WBh[2 * NT * NCH_B * WTILE];
__device__ __align__(16) uint32_t g_sitesH2[BATCH * NNODE * 64];   // fp16x2-packed sites

// ---------------- helpers ----------------
__device__ __forceinline__ float lrelu(float x) { return x > 0.f ? x : 0.01f * x; }
__device__ __forceinline__ uint32_t h2bits(float a, float b) {
    __half2 h = __floats2half2_rn(a, b);
    return *reinterpret_cast<uint32_t*>(&h);
}
__device__ __forceinline__ float2 h2f2(uint32_t u) {
    __half2 h = *reinterpret_cast<__half2*>(&u);
    return __half22float2(h);
}
__device__ __forceinline__ uint32_t smem_u32(const void* p) {
    uint32_t a;
    asm("{ .reg .u64 t; cvta.to.shared.u64 t, %1; cvt.u32.u64 %0, t; }" : "=r"(a) : "l"(p));
    return a;
}
__device__ __forceinline__ void cpasync16(uint32_t saddr, const void* g) {
    asm volatile("cp.async.ca.shared.global [%0], [%1], 16;" :: "r"(saddr), "l"(g));
}
#define CP_COMMIT() asm volatile("cp.async.commit_group;" ::: "memory")
#define CP_WAIT0()  asm volatile("cp.async.wait_group 0;" ::: "memory")
__device__ __forceinline__ void red2(float* addr, float a, float b) {
    asm volatile("red.global.add.v2.f32 [%0], {%1, %2};" :: "l"(addr), "f"(a), "f"(b) : "memory");
}
__device__ __forceinline__ void ldsm4(uint32_t& r0, uint32_t& r1, uint32_t& r2, uint32_t& r3,
                                      uint32_t addr) {
    asm volatile("ldmatrix.sync.aligned.m8n8.x4.shared.b16 {%0,%1,%2,%3}, [%4];"
        : "=r"(r0), "=r"(r1), "=r"(r2), "=r"(r3) : "r"(addr));
}
__device__ __forceinline__ void mma16(float* d, uint32_t a0, uint32_t a1, uint32_t a2, uint32_t a3,
                                      uint32_t b0, uint32_t b1) {
    asm volatile(
        "mma.sync.aligned.m16n8k16.row.col.f32.f16.f16.f32 "
        "{%0,%1,%2,%3},{%4,%5,%6,%7},{%8,%9},{%0,%1,%2,%3};"
        : "+f"(d[0]), "+f"(d[1]), "+f"(d[2]), "+f"(d[3])
        : "r"(a0), "r"(a1), "r"(a2), "r"(a3), "r"(b0), "r"(b1));
}

// ---------------- prep kernels ----------------
__global__ void k_prep(float* __restrict__ out, int n_out, const int* __restrict__ uc,
                       const float* __restrict__ sites,
                       const float* __restrict__ W1a, const float* __restrict__ W2a,
                       const float* __restrict__ W1b, const float* __restrict__ W2b) {
    __shared__ int cnt[NT];
    __shared__ float smw[64 * 129];
    const int blk = blockIdx.x;
    const int tid = threadIdx.x;

    if (blk < PB_ZERO) {
        int i = blk * 256 + tid;
        if (i < (n_out >> 2)) ((float4*)out)[i] = make_float4(0.f, 0.f, 0.f, 0.f);
        if (i < (NEDGE + NT * TM) / 4) ((int4*)g_order)[i] = make_int4(-1, -1, -1, -1);
        return;
    }
    if (blk < PB_ZERO + PB_HIST) {
        int hb = blk - PB_ZERO;
        if (tid < NT) cnt[tid] = 0;
        __syncthreads();
        atomicAdd(&cnt[uc[hb * 256 + tid]], 1);
        __syncthreads();
        if (tid < NT) g_bcnt[hb * NT + tid] = cnt[tid];
        return;
    }
    if (blk < PB_ZERO + PB_HIST + PB_CVTS) {
        // sites fp32 -> fp16x2 pack (coalesced)
        int cb = blk - PB_ZERO - PB_HIST;
        const float4* src = (const float4*)sites;
        uint2* dst = (uint2*)g_sitesH2;
#pragma unroll
        for (int i = 0; i < 8; i++) {
            int q = (cb * 256 + tid) + i * (PB_CVTS * 256);   // float4 index
            float4 v = src[q];
            uint2 o;
            o.x = h2bits(v.x, v.y);
            o.y = h2bits(v.z, v.w);
            dst[q] = o;
        }
        return;
    }
    int wb = blk - PB_ZERO - PB_HIST - PB_CVTS;
    bool isA = wb < 2 * NT * NCH_A;
    int c, pt;
    if (isA) { c = wb % NCH_A; pt = wb / NCH_A; }
    else     { int j = wb - 2 * NT * NCH_A; c = j % NCH_B; pt = j / NCH_B; }
    int t = pt & 3, p = pt >> 2;
    int ld = isA ? DCAT : DOUT;
    const float* W = isA ? (p ? W2a : W1a) : (p ? W2b : W1b);
#pragma unroll
    for (int i = 0; i < 32; i++) {
        int lin = tid + 256 * i;
        int k = lin >> 7, n = lin & 127;
        smw[k * 129 + n] = W[((size_t)t * ld + c * 64 + k) * DOUT + n];
    }
    __syncthreads();
    uint32_t* dst = isA ? (g_WAh + (size_t)(pt * NCH_A + c) * WTILE)
                        : (g_WBh + (size_t)(pt * NCH_B + c) * WTILE);
#pragma unroll
    for (int i = 0; i < 16; i++) {
        int lin = tid + 256 * i;
        int n = lin >> 5, k2 = lin & 31;
        dst[n * WSTR2 + k2] = h2bits(smw[(2 * k2) * 129 + n], smw[(2 * k2 + 1) * 129 + n]);
    }
}

__global__ void k_scan() {
    __shared__ int wsum[8][NT];
    __shared__ int tot[NT];
    int tid = threadIdx.x, lane = tid & 31, w = tid >> 5;
    int4 v = ((const int4*)g_bcnt)[tid];
    int4 orig = v;
#pragma unroll
    for (int d = 1; d < 32; d <<= 1) {
        int x = __shfl_up_sync(~0u, v.x, d), y = __shfl_up_sync(~0u, v.y, d);
        int z = __shfl_up_sync(~0u, v.z, d), q = __shfl_up_sync(~0u, v.w, d);
        if (lane >= d) { v.x += x; v.y += y; v.z += z; v.w += q; }
    }
    if (lane == 31) { wsum[w][0] = v.x; wsum[w][1] = v.y; wsum[w][2] = v.z; wsum[w][3] = v.w; }
    __syncthreads();
    if (tid == 0) {
        int a0 = 0, a1 = 0, a2 = 0, a3 = 0;
        for (int i = 0; i < 8; i++) {
            int t0 = wsum[i][0], t1 = wsum[i][1], t2 = wsum[i][2], t3 = wsum[i][3];
            wsum[i][0] = a0; wsum[i][1] = a1; wsum[i][2] = a2; wsum[i][3] = a3;
            a0 += t0; a1 += t1; a2 += t2; a3 += t3;
        }
        tot[0] = a0; tot[1] = a1; tot[2] = a2; tot[3] = a3;
    }
    __syncthreads();
    int e0 = v.x + wsum[w][0] - orig.x;
    int e1 = v.y + wsum[w][1] - orig.y;
    int e2 = v.z + wsum[w][2] - orig.z;
    int e3 = v.w + wsum[w][3] - orig.w;
    int p0 = 0;
    int p1 = p0 + ((tot[0] + TM - 1) / TM) * TM;
    int p2 = p1 + ((tot[1] + TM - 1) / TM) * TM;
    int p3 = p2 + ((tot[2] + TM - 1) / TM) * TM;
    int p4 = p3 + ((tot[3] + TM - 1) / TM) * TM;
    int4 bb; bb.x = p0 + e0; bb.y = p1 + e1; bb.z = p2 + e2; bb.w = p3 + e3;
    ((int4*)g_bbase)[tid] = bb;
    if (tid == 0) {
        g_poff[0] = p0; g_poff[1] = p1; g_poff[2] = p2; g_poff[3] = p3; g_poff[4] = p4;
    }
}

__global__ void k_scatter(const int* __restrict__ uc) {
    __shared__ int base[NT];
    __shared__ int cur[NT];
    int tid = threadIdx.x;
    if (tid < NT) { base[tid] = g_bbase[blockIdx.x * NT + tid]; cur[tid] = 0; }
    __syncthreads();
    int e = blockIdx.x * 256 + tid;
    int t = uc[e];
    int pos = atomicAdd(&cur[t], 1);
    g_order[base[t] + pos] = e;
}

// ---------------- fused kernel smem layout (u32 units) ----------------
#define OFA    0                       // 2 x 4608 (A chunk double buffer)
#define OFW    9216                    // 2 pair-slots x 2 tiles x 4608 = 18432
#define OFH    27648                   // 2 x (128 x 68) = 17408
#define OFRED  45056
#define OFBIAS 45184                   // 6 x 128
#define OFE    45952
#define OFI1   46080
#define OFI2   46208
#define SMEM_U32 46336
#define SMEM_BYTES (SMEM_U32 * 4)      // 185344

__device__ __forceinline__ void issueWpair(uint32_t sdst, const uint32_t* __restrict__ ga,
                                           const uint32_t* __restrict__ gb, int tid) {
    const uint4* g0 = (const uint4*)ga;
    const uint4* g1 = (const uint4*)gb;
#pragma unroll
    for (int i = 0; i < 5; i++) {
        int lin = tid + TB * i;
        if (lin < 1152) {
            cpasync16(sdst + lin * 16, g0 + lin);
            cpasync16(sdst + WTILE * 4 + lin * 16, g1 + lin);
        }
    }
    CP_COMMIT();
}

// sites chunks 0..3: direct cp.async fp16 gather into staged layout
__device__ __forceinline__ void issueAsites(uint32_t abuf, int b,
                                            const int* sI1, const int* sI2,
                                            int c, int tid) {
    const int* sIdx = (c < 2) ? sI1 : sI2;
    const int coff = (c & 1) * 32;      // u32 offset within the 64-u32 site row
#pragma unroll
    for (int i = 0; i < 2; i++) {
        int lin = tid + TB * i;         // 0..1023 = 128 rows x 8 groups
        int row = lin >> 3, g = (lin & 7) << 2;
        const uint32_t* src = g_sitesH2 + ((size_t)b * NNODE + sIdx[row]) * 64 + coff + g;
        cpasync16(abuf + (uint32_t)(row * ASTR2 + g) * 4, src);
    }
    CP_COMMIT();
}

// bonds chunk 4: fp32 register gather (no reuse -> pre-conversion not worth it)
__device__ __forceinline__ void gatherBonds(float4* pA, const float* __restrict__ bonds, int b,
                                            const int* sE, int tid) {
#pragma unroll
    for (int i = 0; i < 4; i++) {
        int lin = tid + TB * i;
        int row = lin >> 4, col = (lin & 15) << 2;
        int e = sE[row]; if (e < 0) e = 0;
        pA[i] = *(const float4*)(bonds + ((size_t)b * NEDGE + e) * DBOND + col);
    }
}
__device__ __forceinline__ void stageBonds(uint32_t* __restrict__ Ab, const float4* pA, int tid) {
#pragma unroll
    for (int i = 0; i < 4; i++) {
        int lin = tid + TB * i;
        int row = lin >> 4, j = (lin & 15) << 1;
        uint2 v;
        v.x = h2bits(pA[i].x, pA[i].y);
        v.y = h2bits(pA[i].z, pA[i].w);
        *(uint2*)(Ab + row * ASTR2 + j) = v;
    }
}

// merged layer-A chunk: warp tile 32 x 64 over (128 x 256)
__device__ __forceinline__ void mmaMerged(uint32_t aAddr, uint32_t wAddr, float acc[2][8][4]) {
#pragma unroll
    for (int kk = 0; kk < 4; kk++) {
        const uint32_t kb = kk * 32;
        uint32_t bw[16];
        ldsm4(bw[0],  bw[1],  bw[2],  bw[3],  wAddr + kb);
        ldsm4(bw[4],  bw[5],  bw[6],  bw[7],  wAddr + 16 * WSTR2 * 4 + kb);
        ldsm4(bw[8],  bw[9],  bw[10], bw[11], wAddr + 32 * WSTR2 * 4 + kb);
        ldsm4(bw[12], bw[13], bw[14], bw[15], wAddr + 48 * WSTR2 * 4 + kb);
#pragma unroll
        for (int mt = 0; mt < 2; mt++) {
            uint32_t a0, a1, a2, a3;
            ldsm4(a0, a1, a2, a3, aAddr + mt * 16 * ASTR2 * 4 + kb);
#pragma unroll
            for (int nt = 0; nt < 8; nt++)
                mma16(acc[mt][nt], a0, a1, a2, a3, bw[2 * nt], bw[2 * nt + 1]);
        }
    }
}

// layer-B chunk: warp tile 32 x 32
__device__ __forceinline__ void mmaChunkL(uint32_t aAddr, int astrB, uint32_t wAddr,
                                          float acc[2][4][4]) {
#pragma unroll
    for (int kk = 0; kk < 4; kk++) {
        const uint32_t kb = kk * 32;
        uint32_t b00, b01, b10, b11, b20, b21, b30, b31;
        ldsm4(b00, b01, b10, b11, wAddr + kb);
        ldsm4(b20, b21, b30, b31, wAddr + 16 * WSTR2 * 4 + kb);
#pragma unroll
        for (int mt = 0; mt < 2; mt++) {
            uint32_t a0, a1, a2, a3;
            ldsm4(a0, a1, a2, a3, aAddr + mt * 16 * astrB + kb);
            mma16(acc[mt][0], a0, a1, a2, a3, b00, b01);
            mma16(acc[mt][1], a0, a1, a2, a3, b10, b11);
            mma16(acc[mt][2], a0, a1, a2, a3, b20, b21);
            mma16(acc[mt][3], a0, a1, a2, a3, b30, b31);
        }
    }
}

__global__ void __launch_bounds__(TB) k_fused(
    const float* __restrict__ sites, const float* __restrict__ bonds,
    const int* __restrict__ idx1, const int* __restrict__ idx2,
    const float* __restrict__ b1a, const float* __restrict__ b1b,
    const float* __restrict__ b2a, const float* __restrict__ b2b,
    const float* __restrict__ Wa1, const float* __restrict__ ba1,
    const float* __restrict__ Wa2, const float* __restrict__ ba2,
    float* __restrict__ out)
{
    extern __shared__ uint32_t sm[];
    uint32_t* sH0 = sm + OFH;
    uint32_t* sH1 = sm + OFH + 128 * HSTR2;
    float* sRed  = (float*)(sm + OFRED);
    float* sBias = (float*)(sm + OFBIAS);
    int* sE  = (int*)(sm + OFE);
    int* sI1 = (int*)(sm + OFI1);
    int* sI2 = (int*)(sm + OFI2);

    const int tile  = blockIdx.x;
    const int start = tile * TM;
    if (start >= g_poff[NT]) return;
    int t = 0;
#pragma unroll
    for (int i = 1; i < NT; i++) if (start >= g_poff[i]) t = i;

    const int tid  = threadIdx.x;
    const int lane = tid & 31;
    const int wid  = tid >> 5;
    const int wm   = wid & 3;
    const int wn   = wid >> 2;
    const int grp  = lane >> 2;
    const int qq   = lane & 3;

    if (tid < TM) {
        int e = g_order[start + tid];
        sE[tid] = e;
        int es = e < 0 ? 0 : e;
        sI1[tid] = idx1[es];
        sI2[tid] = idx2[es];
    }
    if (tid < 128) {
        sBias[0 * 128 + tid] = b1a[t * DOUT + tid];
        sBias[1 * 128 + tid] = b1b[t * DOUT + tid];
        sBias[2 * 128 + tid] = Wa1[tid];
        sBias[3 * 128 + tid] = b2a[t * DOUT + tid];
        sBias[4 * 128 + tid] = b2b[t * DOUT + tid];
        sBias[5 * 128 + tid] = Wa2[tid];
    }
    __syncthreads();

    // ldmatrix lane offsets
    const int rA = wm * 32 + (lane & 7) + ((lane >> 3) & 1) * 8;
    const int nB = (lane & 7) + ((lane >> 4) & 1) * 8;
    const uint32_t sb = smem_u32(sm);
    const uint32_t aBase = sb + (uint32_t)(rA * ASTR2 + (lane >> 4) * 4) * 4;
    const uint32_t hBase0 = sb + (uint32_t)(OFH + rA * HSTR2 + (lane >> 4) * 4) * 4;
    const uint32_t hBase1 = hBase0 + (uint32_t)(128 * HSTR2) * 4;
    const uint32_t wBaseA = sb + (uint32_t)(OFW + (wn >> 1) * WTILE
                           + ((wn & 1) * 64 + nB) * WSTR2 + ((lane >> 3) & 1) * 4) * 4;
    const uint32_t wBaseB = sb + (uint32_t)(OFW + (wn * 32 + nB) * WSTR2
                           + ((lane >> 3) & 1) * 4) * 4;
    const uint32_t PAIR = (uint32_t)(2 * WTILE) * 4;

    const int bb0 = blockIdx.y * 2;
    const float bg1 = ba1[0], bg2 = ba2[0];
    const int phase = wn >> 1;
    const float* sBlaP = sBias + (phase * 3) * 128;
    uint32_t* sHp = phase ? sH1 : sH0;

    const uint32_t* gWA1 = g_WAh + (size_t)((0 * NT + t) * NCH_A) * WTILE;
    const uint32_t* gWA2 = g_WAh + (size_t)((1 * NT + t) * NCH_A) * WTILE;
    const uint32_t* gWB1 = g_WBh + (size_t)((0 * NT + t) * NCH_B) * WTILE;
    const uint32_t* gWB2 = g_WBh + (size_t)((1 * NT + t) * NCH_B) * WTILE;

    float4 pB[4];            // bonds prefetch only
    uint32_t g1h[16];

    // prologue: W chunk0 pair -> slot0; cp.async A chunk0 -> Abuf0
    issueWpair(sb + OFW * 4, gWA1, gWA2, tid);
    issueAsites(sb + (OFA + 0 * ACH) * 4, bb0, sI1, sI2, 0, tid);

#pragma unroll 1
    for (int bb = bb0; bb < bb0 + 2; ++bb) {
        float acc[2][8][4];
#pragma unroll
        for (int mt = 0; mt < 2; mt++)
#pragma unroll
            for (int nt = 0; nt < 8; nt++)
#pragma unroll
                for (int i = 0; i < 4; i++) acc[mt][nt][i] = 0.f;

        // ---------------- merged layer A: [128x320] @ [320x256] ----------------
#pragma unroll
        for (int c = 0; c < NCH_A; c++) {
            const int s = c & 1;
            if (c == 4) stageBonds(sm + OFA + s * ACH, pB, tid);
            CP_WAIT0();
            __syncthreads();
            if (c + 1 < NCH_A) {
                issueWpair(sb + OFW * 4 + ((c + 1) & 1) * PAIR,
                           gWA1 + (size_t)(c + 1) * WTILE, gWA2 + (size_t)(c + 1) * WTILE, tid);
                if (c + 1 < 4)
                    issueAsites(sb + (OFA + ((c + 1) & 1) * ACH) * 4, bb, sI1, sI2, c + 1, tid);
                else
                    gatherBonds(pB, bonds, bb, sE, tid);
            } else {
                issueWpair(sb + OFW * 4 + PAIR, gWB1, gWB1 + WTILE, tid);   // W1b pair
            }
            mmaMerged(aBase + (uint32_t)(s * ACH) * 4, wBaseA + (s & 1) * PAIR, acc);
        }
        __syncthreads();   // all layer-A MMA done

        // ---- epilogue A: H_phase = fp16(lrelu(acc + bla_phase)) ----
#pragma unroll
        for (int mt = 0; mt < 2; mt++) {
            int r = wm * 32 + mt * 16 + grp;
#pragma unroll
            for (int nt = 0; nt < 8; nt++) {
                int ccl = (wn & 1) * 64 + nt * 8 + 2 * qq;
                int col2 = (wn & 1) * 32 + nt * 4 + qq;
                sHp[r * HSTR2 + col2] =
                    h2bits(lrelu(acc[mt][nt][0] + sBlaP[ccl]), lrelu(acc[mt][nt][1] + sBlaP[ccl + 1]));
                sHp[(r + 8) * HSTR2 + col2] =
                    h2bits(lrelu(acc[mt][nt][2] + sBlaP[ccl]), lrelu(acc[mt][nt][3] + sBlaP[ccl + 1]));
            }
        }
        if (bb == bb0)     // next batch's A chunk0 -> Abuf0 (free: last read was mma c=... buf0 at c=4)
            issueAsites(sb + (OFA + 0 * ACH) * 4, bb0 + 1, sI1, sI2, 0, tid);
        CP_WAIT0();
        __syncthreads();   // H visible + W1b pair resident

        float acc2[2][4][4];
#pragma unroll
        for (int mt = 0; mt < 2; mt++)
#pragma unroll
            for (int nt = 0; nt < 4; nt++)
#pragma unroll
                for (int i = 0; i < 4; i++) acc2[mt][nt][i] = 0.f;

        // ---------------- layer B, phase 0: out1 = H1 @ W1b ----------------
        mmaChunkL(hBase0,       HSTR2 * 4, wBaseB + PAIR,             acc2);
        mmaChunkL(hBase0 + 128, HSTR2 * 4, wBaseB + PAIR + WTILE * 4, acc2);
        issueWpair(sb + OFW * 4, gWB2, gWB2 + WTILE, tid);   // W2b pair -> slot0
        __syncthreads();
        if (tid < TM) sRed[tid] = 0.f;
        __syncthreads();
        // gate dot p0
#pragma unroll
        for (int mt = 0; mt < 2; mt++) {
            int r = wm * 32 + mt * 16 + grp;
            float d0 = 0.f, d1 = 0.f;
#pragma unroll
            for (int nt = 0; nt < 4; nt++) {
                int cc = wn * 32 + nt * 8 + 2 * qq;
                float w0 = sBias[2 * 128 + cc], w1 = sBias[2 * 128 + cc + 1];
                d0 += lrelu(acc2[mt][nt][0] + sBias[1 * 128 + cc]) * w0
                    + lrelu(acc2[mt][nt][1] + sBias[1 * 128 + cc + 1]) * w1;
                d1 += lrelu(acc2[mt][nt][2] + sBias[1 * 128 + cc]) * w0
                    + lrelu(acc2[mt][nt][3] + sBias[1 * 128 + cc + 1]) * w1;
            }
            d0 += __shfl_xor_sync(0xffffffffu, d0, 1);
            d0 += __shfl_xor_sync(0xffffffffu, d0, 2);
            d1 += __shfl_xor_sync(0xffffffffu, d1, 1);
            d1 += __shfl_xor_sync(0xffffffffu, d1, 2);
            if (qq == 0) {
                atomicAdd(&sRed[r], d0);
                atomicAdd(&sRed[r + 8], d1);
            }
        }
        CP_WAIT0();
        __syncthreads();
        // park g1 = sig0 * lrelu(out1 + b1b)
#pragma unroll
        for (int mt = 0; mt < 2; mt++) {
            int r = wm * 32 + mt * 16 + grp;
            float sig0 = 1.f / (1.f + __expf(-(sRed[r] + bg1)));
            float sig1 = 1.f / (1.f + __expf(-(sRed[r + 8] + bg1)));
#pragma unroll
            for (int nt = 0; nt < 4; nt++) {
                int cc = wn * 32 + nt * 8 + 2 * qq;
                int gi = (mt * 4 + nt) * 2;
                g1h[gi]     = h2bits(sig0 * lrelu(acc2[mt][nt][0] + sBias[1 * 128 + cc]),
                                     sig0 * lrelu(acc2[mt][nt][1] + sBias[1 * 128 + cc + 1]));
                g1h[gi + 1] = h2bits(sig1 * lrelu(acc2[mt][nt][2] + sBias[1 * 128 + cc]),
                                     sig1 * lrelu(acc2[mt][nt][3] + sBias[1 * 128 + cc + 1]));
            }
        }

        // ---------------- layer B, phase 1: out2 = H2 @ W2b ----------------
#pragma unroll
        for (int mt = 0; mt < 2; mt++)
#pragma unroll
            for (int nt = 0; nt < 4; nt++)
#pragma unroll
                for (int i = 0; i < 4; i++) acc2[mt][nt][i] = 0.f;
        mmaChunkL(hBase1,       HSTR2 * 4, wBaseB,             acc2);
        mmaChunkL(hBase1 + 128, HSTR2 * 4, wBaseB + WTILE * 4, acc2);
        __syncthreads();
        if (bb == bb0)     // next batch's layer-A chunk0 pair -> slot0
            issueWpair(sb + OFW * 4, gWA1, gWA2, tid);
        if (tid < TM) sRed[tid] = 0.f;
        __syncthreads();
        // gate dot p1
#pragma unroll
        for (int mt = 0; mt < 2; mt++) {
            int r = wm * 32 + mt * 16 + grp;
            float d0 = 0.f, d1 = 0.f;
#pragma unroll
            for (int nt = 0; nt < 4; nt++) {
                int cc = wn * 32 + nt * 8 + 2 * qq;
                float w0 = sBias[5 * 128 + cc], w1 = sBias[5 * 128 + cc + 1];
                d0 += lrelu(acc2[mt][nt][0] + sBias[4 * 128 + cc]) * w0
                    + lrelu(acc2[mt][nt][1] + sBias[4 * 128 + cc + 1]) * w1;
                d1 += lrelu(acc2[mt][nt][2] + sBias[4 * 128 + cc]) * w0
                    + lrelu(acc2[mt][nt][3] + sBias[4 * 128 + cc + 1]) * w1;
            }
            d0 += __shfl_xor_sync(0xffffffffu, d0, 1);
            d0 += __shfl_xor_sync(0xffffffffu, d0, 2);
            d1 += __shfl_xor_sync(0xffffffffu, d1, 1);
            d1 += __shfl_xor_sync(0xffffffffu, d1, 2);
            if (qq == 0) {
                atomicAdd(&sRed[r], d0);
                atomicAdd(&sRed[r + 8], d1);
            }
        }
        __syncthreads();
        // combine g1 + g2 and scatter
#pragma unroll
        for (int mt = 0; mt < 2; mt++) {
            int r = wm * 32 + mt * 16 + grp;
            float sig0 = 1.f / (1.f + __expf(-(sRed[r] + bg2)));
            float sig1 = 1.f / (1.f + __expf(-(sRed[r + 8] + bg2)));
            bool v0 = sE[r] >= 0, v1 = sE[r + 8] >= 0;
            float* d0p = out + ((size_t)bb * NNODE + sI2[r]) * DOUT;
            float* d1p = out + ((size_t)bb * NNODE + sI2[r + 8]) * DOUT;
#pragma unroll
            for (int nt = 0; nt < 4; nt++) {
                int cc = wn * 32 + nt * 8 + 2 * qq;
                int gi = (mt * 4 + nt) * 2;
                float2 ga = h2f2(g1h[gi]);
                float2 gb = h2f2(g1h[gi + 1]);
                if (v0) {
                    red2(d0p + cc,
                         sig0 * lrelu(acc2[mt][nt][0] + sBias[4 * 128 + cc]) + ga.x,
                         sig0 * lrelu(acc2[mt][nt][1] + sBias[4 * 128 + cc + 1]) + ga.y);
                }
                if (v1) {
                    red2(d1p + cc,
                         sig1 * lrelu(acc2[mt][nt][2] + sBias[4 * 128 + cc]) + gb.x,
                         sig1 * lrelu(acc2[mt][nt][3] + sBias[4 * 128 + cc + 1]) + gb.y);
                }
            }
        }
    } // bb
}

// ---------------- launcher ----------------
extern "C" void kernel_launch(void* const* d_in, const int* in_sizes, int n_in,
                              void* d_out, int out_size) {
    (void)in_sizes; (void)n_in;
    const float* sites = (const float*)d_in[0];
    const float* bonds = (const float*)d_in[1];
    const int*   idx1  = (const int*)d_in[2];
    const int*   idx2  = (const int*)d_in[3];
    const int*   uc    = (const int*)d_in[4];
    const float* W1a = (const float*)d_in[5];
    const float* b1a = (const float*)d_in[6];
    const float* W1b = (const float*)d_in[7];
    const float* b1b = (const float*)d_in[8];
    const float* W2a = (const float*)d_in[9];
    const float* b2a = (const float*)d_in[10];
    const float* W2b = (const float*)d_in[11];
    const float* b2b = (const float*)d_in[12];
    const float* Wa1 = (const float*)d_in[13];
    const float* ba1 = (const float*)d_in[14];
    const float* Wa2 = (const float*)d_in[15];
    const float* ba2 = (const float*)d_in[16];
    float* out = (float*)d_out;

    cudaFuncSetAttribute(k_fused, cudaFuncAttributeMaxDynamicSharedMemorySize, SMEM_BYTES);

    k_prep<<<PB_ZERO + PB_HIST + PB_CVTS + PB_PREPW, 256>>>(out, out_size, uc, sites,
                                                            W1a, W2a, W1b, W2b);
    k_scan<<<1, 256>>>();
    k_scatter<<<NHB, 256>>>(uc);
    dim3 grid(NTILES, BATCH / 2);
    k_fused<<<grid, TB, SMEM_BYTES>>>(sites, bonds, idx1, idx2,
                                      b1a, b1b, b2a, b2b,
                                      Wa1, ba1, Wa2, ba2, out);
}